// round 15
// baseline (speedup 1.0000x reference)
#include <cuda_runtime.h>
#include <cuda_fp16.h>
#include <cstdint>
#include <math.h>

#define BATCH 4
#define SEQ   2048
#define CDIM  2048
#define HDIM  128
#define ROWS  (BATCH*SEQ)
#define NSPLIT 4

// ---------------------------------------------------------------------------
// Device scratch (allocation-free)
// ---------------------------------------------------------------------------
__device__ __align__(16) __half g_wt[(size_t)3*HDIM*CDIM];   // W^T fp16 [384][2048]
__device__ __align__(16) __half g_qh[(size_t)ROWS*HDIM];     // q*scale*log2e fp16
__device__ __align__(16) __half g_kh[(size_t)ROWS*HDIM];     // k fp16
__device__ __align__(16) __half g_vh[(size_t)ROWS*HDIM];     // v fp16
__device__ __align__(16) __half g_poh[NSPLIT][(size_t)ROWS*HDIM]; // partial O fp16
__device__ float2 g_pml[NSPLIT][ROWS];                       // partial (m, l), m in log2 domain

// ---------------------------------------------------------------------------
// Helpers (vanilla sm_80-era PTX: ldmatrix / mma.sync / cp.async)
// ---------------------------------------------------------------------------
__device__ __forceinline__ uint32_t smem_u32(const void* p) {
    uint32_t a;
    asm("{ .reg .u64 t; cvta.to.shared.u64 t, %1; cvt.u32.u64 %0, t; }"
        : "=r"(a) : "l"(p));
    return a;
}
#define CP_ASYNC16(dst, src) \
    asm volatile("cp.async.cg.shared.global [%0], [%1], 16;" \
                 :: "r"(dst), "l"(src) : "memory")
#define CP_COMMIT() asm volatile("cp.async.commit_group;" ::: "memory")
#define CP_WAIT1()  asm volatile("cp.async.wait_group 1;" ::: "memory")
#define CP_WAIT0()  asm volatile("cp.async.wait_group 0;" ::: "memory")

#define LDSM_X4(r0,r1,r2,r3,addr) \
    asm volatile("ldmatrix.sync.aligned.m8n8.x4.shared.b16 {%0,%1,%2,%3}, [%4];" \
                 : "=r"(r0),"=r"(r1),"=r"(r2),"=r"(r3) : "r"(addr))
#define LDSM_X4T(r0,r1,r2,r3,addr) \
    asm volatile("ldmatrix.sync.aligned.m8n8.x4.trans.shared.b16 {%0,%1,%2,%3}, [%4];" \
                 : "=r"(r0),"=r"(r1),"=r"(r2),"=r"(r3) : "r"(addr))

__device__ __forceinline__ void mma_f16(float c[4], uint32_t a0, uint32_t a1,
                                        uint32_t a2, uint32_t a3,
                                        uint32_t b0, uint32_t b1)
{
    asm volatile(
        "mma.sync.aligned.m16n8k16.row.col.f32.f16.f16.f32 "
        "{%0,%1,%2,%3},{%4,%5,%6,%7},{%8,%9},{%0,%1,%2,%3};"
        : "+f"(c[0]), "+f"(c[1]), "+f"(c[2]), "+f"(c[3])
        : "r"(a0), "r"(a1), "r"(a2), "r"(a3), "r"(b0), "r"(b1));
}
// pack {lo, hi} floats -> f16x2 register
__device__ __forceinline__ uint32_t pack_h2(float lo, float hi) {
    uint32_t d;
    asm("cvt.rn.f16x2.f32 %0, %1, %2;" : "=r"(d) : "f"(hi), "f"(lo));
    return d;
}
__device__ __forceinline__ float ex2f(float x) {
    float r;
    asm("ex2.approx.f32 %0, %1;" : "=f"(r) : "f"(x));
    return r;
}

// ---------------------------------------------------------------------------
// Prep: transpose W[2048][128] -> W^T fp16 rows [z*128 + n][k]
// ---------------------------------------------------------------------------
__global__ __launch_bounds__(256) void prep_w_kernel(
    const float* __restrict__ wq, const float* __restrict__ wk, const float* __restrict__ wv)
{
    __shared__ float t[32][129];
    const float* W = (blockIdx.z == 0) ? wq : ((blockIdx.z == 1) ? wk : wv);
    const int k0 = blockIdx.x * 32;
    const int tid = threadIdx.x;

    #pragma unroll
    for (int rep = 0; rep < 4; rep++) {
        int i  = tid + rep * 256;          // 0..1023
        int kk = i >> 5, cc = i & 31;
        float4 v = reinterpret_cast<const float4*>(
            W + (size_t)(k0 + kk) * HDIM)[cc];
        t[kk][cc*4+0] = v.x;
        t[kk][cc*4+1] = v.y;
        t[kk][cc*4+2] = v.z;
        t[kk][cc*4+3] = v.w;
    }
    __syncthreads();

    const int tx = tid & 31;
    const int ty = tid >> 5;
    #pragma unroll
    for (int r = 0; r < 128; r += 8) {
        int nl = ty + r;
        size_t o = (size_t)(blockIdx.z * HDIM + nl) * CDIM + (k0 + tx);
        g_wt[o] = __float2half_rn(t[tx][nl]);
    }
}

// ---------------------------------------------------------------------------
// Fused QKV GEMM, fp16 HMMA, N-split x2 for occupancy (R7/R9/R11-proven).
// Block: 64 rows x 192 cols, BK=32.  256 thr = 8 warps (2 m x 4 n),
// warp tile 32x48.  Grid (128, 2) = 256 CTAs -> 2 CTAs/SM resident.
// A: LDG fp32 -> cvt -> STS fp16 (reg pipelined).  B: cp.async 2-stage.
// ---------------------------------------------------------------------------
#define GQ_ROWH    40
#define GQ_A_BYTES (64*GQ_ROWH*2)              // 5120
#define GQ_B_BYTES (192*GQ_ROWH*2)             // 15360
#define GQ_STAGE   (GQ_A_BYTES + GQ_B_BYTES)   // 20480
#define GQ_SMEM    (2*GQ_STAGE)                // 40960

__device__ __forceinline__ void gemm_issueB(uint32_t smb, int stage, int ki,
                                            int n0, int tid)
{
    const int k0 = ki * 32;
    const uint32_t sb = smb + stage * GQ_STAGE + GQ_A_BYTES;
    #pragma unroll
    for (int rep = 0; rep < 3; rep++) {
        int i = tid + rep * 256;               // 0..767
        int row = i >> 2, c = i & 3;           // row 0..191
        uint32_t dst = sb + (row * GQ_ROWH + c * 8) * 2;
        CP_ASYNC16(dst, g_wt + (size_t)(n0 + row) * CDIM + k0 + c * 8);
    }
    CP_COMMIT();
}

__global__ __launch_bounds__(256, 2) void qkv_gemm_kernel(
    const float* __restrict__ x,
    const float* __restrict__ bq, const float* __restrict__ bk, const float* __restrict__ bv)
{
    extern __shared__ char dsm[];
    const uint32_t smb = smem_u32(dsm);

    const int tid  = threadIdx.x;
    const int lane = tid & 31;
    const int wid  = tid >> 5;
    const int wm   = wid & 1;
    const int wn   = wid >> 1;
    const int m0   = blockIdx.x * 64;
    const int n0   = blockIdx.y * 192;

    const int rbase = (lane & 7) + ((lane >> 3) & 1) * 8;
    const int khalf = ((lane >> 4) & 1) * 8;
    const int g = lane >> 2, t = lane & 3;

    const int arow = tid >> 2;
    const int acol = (tid & 3) * 8;
    const float* aptr = x + (size_t)(m0 + arow) * CDIM + acol;
    const uint32_t asts = (uint32_t)(arow * GQ_ROWH + acol) * 2;

    float C[2][6][4];
    #pragma unroll
    for (int a = 0; a < 2; a++)
        #pragma unroll
        for (int b = 0; b < 6; b++)
            #pragma unroll
            for (int e = 0; e < 4; e++) C[a][b][e] = 0.f;

    float4 ra0 = *reinterpret_cast<const float4*>(aptr);
    float4 ra1 = *reinterpret_cast<const float4*>(aptr + 4);
    gemm_issueB(smb, 0, 0, n0, tid);

    const int NIT = CDIM / 32;
    for (int ki = 0; ki < NIT; ki++) {
        const int st = ki & 1;
        {
            uint4 u;
            u.x = pack_h2(ra0.x, ra0.y);
            u.y = pack_h2(ra0.z, ra0.w);
            u.z = pack_h2(ra1.x, ra1.y);
            u.w = pack_h2(ra1.z, ra1.w);
            *reinterpret_cast<uint4*>(dsm + st * GQ_STAGE + asts) = u;
        }
        if (ki + 1 < NIT) {
            const float* ap = aptr + (ki + 1) * 32;
            ra0 = *reinterpret_cast<const float4*>(ap);
            ra1 = *reinterpret_cast<const float4*>(ap + 4);
            gemm_issueB(smb, st ^ 1, ki + 1, n0, tid);
            CP_WAIT1();
        } else {
            CP_WAIT0();
        }
        __syncthreads();

        const uint32_t sA = smb + st * GQ_STAGE;
        const uint32_t sB = sA + GQ_A_BYTES;

        #pragma unroll
        for (int ks = 0; ks < 2; ks++) {
            const int k0h = ks * 16 + khalf;
            uint32_t a[2][4];
            #pragma unroll
            for (int mt = 0; mt < 2; mt++) {
                int row = wm * 32 + mt * 16 + rbase;
                LDSM_X4(a[mt][0], a[mt][1], a[mt][2], a[mt][3],
                        sA + (row * GQ_ROWH + k0h) * 2);
            }
            #pragma unroll
            for (int np = 0; np < 3; np++) {
                int nrow = wn * 48 + np * 16 + rbase;
                uint32_t b0, b1, b2, b3;
                LDSM_X4(b0, b1, b2, b3, sB + (nrow * GQ_ROWH + k0h) * 2);
                #pragma unroll
                for (int mt = 0; mt < 2; mt++) {
                    mma_f16(C[mt][2*np],   a[mt][0],a[mt][1],a[mt][2],a[mt][3], b0, b2);
                    mma_f16(C[mt][2*np+1], a[mt][0],a[mt][1],a[mt][2],a[mt][3], b1, b3);
                }
            }
        }
        __syncthreads();
    }

    const float scale = 0.031880108165697356f;  // log2(e)/sqrt(2048)
    #pragma unroll
    for (int mt = 0; mt < 2; mt++) {
        #pragma unroll
        for (int nt = 0; nt < 6; nt++) {
            int colg = n0 + wn * 48 + nt * 8 + 2 * t;
            int mat  = colg >> 7;
            int c0   = colg & 127;
            const float* bias = (mat == 0) ? bq : ((mat == 1) ? bk : bv);
            __half* dst       = (mat == 0) ? g_qh : ((mat == 1) ? g_kh : g_vh);
            float sc = (mat == 0) ? scale : 1.f;
            float2 b2 = *reinterpret_cast<const float2*>(bias + c0);
            #pragma unroll
            for (int half = 0; half < 2; half++) {
                int row = m0 + wm * 32 + mt * 16 + g + 8 * half;
                float v0 = (C[mt][nt][2*half]   + b2.x) * sc;
                float v1 = (C[mt][nt][2*half+1] + b2.y) * sc;
                __half2 h; h.x = __float2half_rn(v0); h.y = __float2half_rn(v1);
                *reinterpret_cast<__half2*>(dst + (size_t)row * HDIM + c0) = h;
            }
        }
    }
}

// ---------------------------------------------------------------------------
// Flash attention, split-K x4, f32-acc S MMA, ex2 softmax, fp16 partial O,
// diagonal-tile MMA skipping, prologue-overlapped K/V loads,
// LPT CTA ordering (heavy q-blocks launch first).
// 128 thr = 4 warps, 64 q/CTA, key tiles of 64.
// ---------------------------------------------------------------------------
#define A_TILE  16384                       // one 64x128 fp16 tile
#define A_BUF   (2*A_TILE)                  // K | V per stage
#define A_SMEM  (3*A_BUF)                   // 98304

__device__ __forceinline__ void attn_issue_tile(uint32_t smb, int stage,
                                                int rowbase, int kt, int tid)
{
    const uint32_t sb = smb + stage * A_BUF;
    #pragma unroll
    for (int rep = 0; rep < 16; rep++) {
        int i   = tid + rep * 128;          // 0..2047
        int arr = i >> 10;
        int rem = i & 1023;
        int r = rem >> 4, c = rem & 15;
        uint32_t dst = sb + arr * A_TILE + r * 256 + ((c ^ (r & 7)) * 16);
        const __half* src = (arr == 0 ? g_kh : g_vh)
                          + (size_t)(rowbase + kt * 64 + r) * HDIM + c * 8;
        CP_ASYNC16(dst, src);
    }
    CP_COMMIT();
}

__global__ __launch_bounds__(128) void attn_kernel()
{
    extern __shared__ char dsm[];
    const uint32_t smb = smem_u32(dsm);

    const int tid  = threadIdx.x;
    const int lane = tid & 31;
    const int w    = tid >> 5;
    // LPT ordering: heavy q-blocks (large bx = more key tiles) first.
    const int bx   = gridDim.x - 1 - blockIdx.x;
    const int h    = blockIdx.y;            // key-split index (0..3)
    const int b    = blockIdx.z;            // batch
    const int q0   = bx * 64;
    const int rowbase = b * SEQ;

    const int T  = bx + 1;                  // total key tiles for this q block
    const int kb = (h * T) >> 2;
    const int ke = ((h + 1) * T) >> 2;

    const int g = lane >> 2, t = lane & 3;
    const int rbase = (lane & 7) + ((lane >> 3) & 1) * 8;
    const int chalf = (lane >> 4) & 1;

    float o[16][4];
    #pragma unroll
    for (int n = 0; n < 16; n++)
        #pragma unroll
        for (int e = 0; e < 4; e++) o[n][e] = 0.f;
    float m0 = -INFINITY, m1 = -INFINITY, l0 = 0.f, l1 = 0.f;

    if (kb < ke) {
        attn_issue_tile(smb, 0, rowbase, kb, tid);
        if (kb + 1 < ke) attn_issue_tile(smb, 1, rowbase, kb + 1, tid);

        // Stage Q into stage-2 K region (first overwritten at kt=kb+2).
        #pragma unroll
        for (int rep = 0; rep < 8; rep++) {
            int i = tid + rep * 128;
            int r = i >> 4, c = i & 15;
            uint4 v = *reinterpret_cast<const uint4*>(
                g_qh + (size_t)(rowbase + q0 + r) * HDIM + c * 8);
            *reinterpret_cast<uint4*>(dsm + 2 * A_BUF + r * 256 + ((c ^ (r & 7)) * 16)) = v;
        }
        __syncthreads();

        uint32_t qf[8][4];
        {
            const uint32_t qb = smb + 2 * A_BUF;
            int row = w * 16 + rbase;
            #pragma unroll
            for (int kc = 0; kc < 8; kc++) {
                int ch = 2 * kc + chalf;
                LDSM_X4(qf[kc][0], qf[kc][1], qf[kc][2], qf[kc][3],
                        qb + row * 256 + ((ch ^ (row & 7)) * 16));
            }
        }

        for (int kt = kb; kt < ke; kt++) {
            const int st = (kt - kb) % 3;
            if (kt + 1 < ke) CP_WAIT1(); else CP_WAIT0();
            __syncthreads();
            if (kt + 2 < ke) attn_issue_tile(smb, (st + 2) % 3, rowbase, kt + 2, tid);

            const uint32_t kbuf = smb + st * A_BUF;
            const uint32_t vbuf = kbuf + A_TILE;
            const bool diag = (kt == bx);

            float s[8][4];
            #pragma unroll
            for (int j = 0; j < 8; j++)
                #pragma unroll
                for (int e = 0; e < 4; e++) s[j][e] = 0.f;

            #pragma unroll
            for (int jp = 0; jp < 4; jp++) {
                if (diag && jp > w) break;
                int krow = jp * 16 + rbase;
                #pragma unroll
                for (int kc = 0; kc < 8; kc++) {
                    int ch = 2 * kc + chalf;
                    uint32_t b0, b1, b2, b3;
                    LDSM_X4(b0, b1, b2, b3, kbuf + krow * 256 + ((ch ^ (krow & 7)) * 16));
                    mma_f16(s[2*jp],   qf[kc][0], qf[kc][1], qf[kc][2], qf[kc][3], b0, b2);
                    mma_f16(s[2*jp+1], qf[kc][0], qf[kc][1], qf[kc][2], qf[kc][3], b1, b3);
                }
            }

            if (diag) {
                #pragma unroll
                for (int j = 0; j < 8; j++) {
                    int key = 8 * j + 2 * t;
                    int qr0 = 16 * w + g, qr1 = qr0 + 8;
                    if (key     > qr0) s[j][0] = -INFINITY;
                    if (key + 1 > qr0) s[j][1] = -INFINITY;
                    if (key     > qr1) s[j][2] = -INFINITY;
                    if (key + 1 > qr1) s[j][3] = -INFINITY;
                }
            }

            float r0 = -INFINITY, r1 = -INFINITY;
            #pragma unroll
            for (int j = 0; j < 8; j++) {
                r0 = fmaxf(r0, fmaxf(s[j][0], s[j][1]));
                r1 = fmaxf(r1, fmaxf(s[j][2], s[j][3]));
            }
            r0 = fmaxf(r0, __shfl_xor_sync(0xffffffffu, r0, 1));
            r0 = fmaxf(r0, __shfl_xor_sync(0xffffffffu, r0, 2));
            r1 = fmaxf(r1, __shfl_xor_sync(0xffffffffu, r1, 1));
            r1 = fmaxf(r1, __shfl_xor_sync(0xffffffffu, r1, 2));

            float mn0 = fmaxf(m0, r0), mn1 = fmaxf(m1, r1);
            float cr0 = ex2f(m0 - mn0), cr1 = ex2f(m1 - mn1);

            float rs0 = 0.f, rs1 = 0.f;
            #pragma unroll
            for (int j = 0; j < 8; j++) {
                s[j][0] = ex2f(s[j][0] - mn0);
                s[j][1] = ex2f(s[j][1] - mn0);
                s[j][2] = ex2f(s[j][2] - mn1);
                s[j][3] = ex2f(s[j][3] - mn1);
                rs0 += s[j][0] + s[j][1];
                rs1 += s[j][2] + s[j][3];
            }
            rs0 += __shfl_xor_sync(0xffffffffu, rs0, 1);
            rs0 += __shfl_xor_sync(0xffffffffu, rs0, 2);
            rs1 += __shfl_xor_sync(0xffffffffu, rs1, 1);
            rs1 += __shfl_xor_sync(0xffffffffu, rs1, 2);

            l0 = l0 * cr0 + rs0;
            l1 = l1 * cr1 + rs1;
            m0 = mn0; m1 = mn1;
            #pragma unroll
            for (int n = 0; n < 16; n++) {
                o[n][0] *= cr0; o[n][1] *= cr0;
                o[n][2] *= cr1; o[n][3] *= cr1;
            }

            uint32_t ap[4][4];
            #pragma unroll
            for (int u = 0; u < 4; u++)
                #pragma unroll
                for (int half = 0; half < 2; half++)
                    #pragma unroll
                    for (int sub = 0; sub < 2; sub++)
                        ap[u][half + 2*sub] = pack_h2(s[2*u + sub][2*half],
                                                      s[2*u + sub][2*half + 1]);

            #pragma unroll
            for (int u = 0; u < 4; u++) {
                if (diag && u > w) break;
                int krow = u * 16 + rbase;
                #pragma unroll
                for (int ntp = 0; ntp < 8; ntp++) {
                    int ch = 2 * ntp + chalf;
                    uint32_t h0, h1, h2, h3;
                    LDSM_X4T(h0, h1, h2, h3, vbuf + krow * 256 + ((ch ^ (krow & 7)) * 16));
                    mma_f16(o[2*ntp],   ap[u][0],ap[u][1],ap[u][2],ap[u][3], h0, h1);
                    mma_f16(o[2*ntp+1], ap[u][0],ap[u][1],ap[u][2],ap[u][3], h2, h3);
                }
            }
        }
    }

    int row0 = rowbase + q0 + 16 * w + g;
    __half* po = g_poh[h];
    #pragma unroll
    for (int j = 0; j < 16; j++) {
        int col = 8 * j + 2 * t;
        *reinterpret_cast<uint32_t*>(po + (size_t)row0 * HDIM + col)       = pack_h2(o[j][0], o[j][1]);
        *reinterpret_cast<uint32_t*>(po + (size_t)(row0 + 8) * HDIM + col) = pack_h2(o[j][2], o[j][3]);
    }
    if (t == 0) {
        float2 a; a.x = m0; a.y = l0;
        float2 c; c.x = m1; c.y = l1;
        g_pml[h][row0]     = a;
        g_pml[h][row0 + 8] = c;
    }
}

// ---------------------------------------------------------------------------
// Combine the four key-split fp16 partials -> final fp32 output
// ---------------------------------------------------------------------------
__global__ __launch_bounds__(128) void combine_kernel(float* __restrict__ out)
{
    int gid = blockIdx.x * 128 + threadIdx.x;   // < ROWS*16 (uint4 = 8 halves)
    int q = gid >> 4;
    float2 ml[NSPLIT];
    float M = -INFINITY;
    #pragma unroll
    for (int i = 0; i < NSPLIT; i++) { ml[i] = g_pml[i][q]; M = fmaxf(M, ml[i].x); }
    float e[NSPLIT], den = 0.f;
    #pragma unroll
    for (int i = 0; i < NSPLIT; i++) { e[i] = ex2f(ml[i].x - M); den += ml[i].y * e[i]; }
    float inv = 1.f / den;

    float acc[8];
    #pragma unroll
    for (int j = 0; j < 8; j++) acc[j] = 0.f;
    #pragma unroll
    for (int i = 0; i < NSPLIT; i++) {
        uint4 u = reinterpret_cast<const uint4*>(g_poh[i])[gid];
        const uint32_t* uu = &u.x;
        #pragma unroll
        for (int p = 0; p < 4; p++) {
            float2 f = __half22float2(*reinterpret_cast<const __half2*>(&uu[p]));
            acc[2*p]   = fmaf(f.x, e[i], acc[2*p]);
            acc[2*p+1] = fmaf(f.y, e[i], acc[2*p+1]);
        }
    }
    float4 r0, r1;
    r0.x = acc[0]*inv; r0.y = acc[1]*inv; r0.z = acc[2]*inv; r0.w = acc[3]*inv;
    r1.x = acc[4]*inv; r1.y = acc[5]*inv; r1.z = acc[6]*inv; r1.w = acc[7]*inv;
    reinterpret_cast<float4*>(out)[2*gid]   = r0;
    reinterpret_cast<float4*>(out)[2*gid+1] = r1;
}

// ---------------------------------------------------------------------------
extern "C" void kernel_launch(void* const* d_in, const int* in_sizes, int n_in,
                              void* d_out, int out_size)
{
    const float* x  = (const float*)d_in[0];
    const float* wq = (const float*)d_in[1];
    const float* bq = (const float*)d_in[2];
    const float* wk = (const float*)d_in[3];
    const float* bk = (const float*)d_in[4];
    const float* wv = (const float*)d_in[5];
    const float* bv = (const float*)d_in[6];
    float* out = (float*)d_out;

    cudaFuncSetAttribute(qkv_gemm_kernel,
                         cudaFuncAttributeMaxDynamicSharedMemorySize, GQ_SMEM);
    cudaFuncSetAttribute(attn_kernel,
                         cudaFuncAttributeMaxDynamicSharedMemorySize, A_SMEM);

    prep_w_kernel<<<dim3(CDIM/32, 1, 3), 256>>>(wq, wk, wv);
    qkv_gemm_kernel<<<dim3(ROWS/64, 2), 256, GQ_SMEM>>>(x, bq, bk, bv);
    attn_kernel<<<dim3(SEQ/64, NSPLIT, BATCH), 128, A_SMEM>>>();
    combine_kernel<<<ROWS*16/128, 128>>>(out);
}

// round 16
// speedup vs baseline: 1.0621x; 1.0621x over previous
#include <cuda_runtime.h>
#include <cuda_fp16.h>
#include <cstdint>
#include <math.h>

#define BATCH 4
#define SEQ   2048
#define CDIM  2048
#define HDIM  128
#define ROWS  (BATCH*SEQ)
#define NSPLIT 4

// ---------------------------------------------------------------------------
// Device scratch (allocation-free)
// ---------------------------------------------------------------------------
__device__ __align__(16) __half g_wt[(size_t)3*HDIM*CDIM];   // W^T fp16 [384][2048]
__device__ __align__(16) __half g_qh[(size_t)ROWS*HDIM];     // q*scale*log2e fp16
__device__ __align__(16) __half g_kh[(size_t)ROWS*HDIM];     // k fp16
__device__ __align__(16) __half g_vh[(size_t)ROWS*HDIM];     // v fp16
__device__ __align__(16) __half g_poh[NSPLIT][(size_t)ROWS*HDIM]; // partial O fp16
__device__ float2 g_pml[NSPLIT][ROWS];                       // partial (m, l), m in log2 domain

// ---------------------------------------------------------------------------
// Helpers (vanilla sm_80-era PTX: ldmatrix / mma.sync / cp.async)
// ---------------------------------------------------------------------------
__device__ __forceinline__ uint32_t smem_u32(const void* p) {
    uint32_t a;
    asm("{ .reg .u64 t; cvta.to.shared.u64 t, %1; cvt.u32.u64 %0, t; }"
        : "=r"(a) : "l"(p));
    return a;
}
#define CP_ASYNC16(dst, src) \
    asm volatile("cp.async.cg.shared.global [%0], [%1], 16;" \
                 :: "r"(dst), "l"(src) : "memory")
#define CP_COMMIT() asm volatile("cp.async.commit_group;" ::: "memory")
#define CP_WAIT1()  asm volatile("cp.async.wait_group 1;" ::: "memory")
#define CP_WAIT0()  asm volatile("cp.async.wait_group 0;" ::: "memory")

#define LDSM_X4(r0,r1,r2,r3,addr) \
    asm volatile("ldmatrix.sync.aligned.m8n8.x4.shared.b16 {%0,%1,%2,%3}, [%4];" \
                 : "=r"(r0),"=r"(r1),"=r"(r2),"=r"(r3) : "r"(addr))
#define LDSM_X4T(r0,r1,r2,r3,addr) \
    asm volatile("ldmatrix.sync.aligned.m8n8.x4.trans.shared.b16 {%0,%1,%2,%3}, [%4];" \
                 : "=r"(r0),"=r"(r1),"=r"(r2),"=r"(r3) : "r"(addr))

__device__ __forceinline__ void mma_f16(float c[4], uint32_t a0, uint32_t a1,
                                        uint32_t a2, uint32_t a3,
                                        uint32_t b0, uint32_t b1)
{
    asm volatile(
        "mma.sync.aligned.m16n8k16.row.col.f32.f16.f16.f32 "
        "{%0,%1,%2,%3},{%4,%5,%6,%7},{%8,%9},{%0,%1,%2,%3};"
        : "+f"(c[0]), "+f"(c[1]), "+f"(c[2]), "+f"(c[3])
        : "r"(a0), "r"(a1), "r"(a2), "r"(a3), "r"(b0), "r"(b1));
}
// pack {lo, hi} floats -> f16x2 register
__device__ __forceinline__ uint32_t pack_h2(float lo, float hi) {
    uint32_t d;
    asm("cvt.rn.f16x2.f32 %0, %1, %2;" : "=r"(d) : "f"(hi), "f"(lo));
    return d;
}
__device__ __forceinline__ float ex2f(float x) {
    float r;
    asm("ex2.approx.f32 %0, %1;" : "=f"(r) : "f"(x));
    return r;
}

// ---------------------------------------------------------------------------
// Prep: transpose W[2048][128] -> W^T fp16 rows [z*128 + n][k]
// ---------------------------------------------------------------------------
__global__ __launch_bounds__(256) void prep_w_kernel(
    const float* __restrict__ wq, const float* __restrict__ wk, const float* __restrict__ wv)
{
    __shared__ float t[32][129];
    const float* W = (blockIdx.z == 0) ? wq : ((blockIdx.z == 1) ? wk : wv);
    const int k0 = blockIdx.x * 32;
    const int tid = threadIdx.x;

    #pragma unroll
    for (int rep = 0; rep < 4; rep++) {
        int i  = tid + rep * 256;          // 0..1023
        int kk = i >> 5, cc = i & 31;
        float4 v = reinterpret_cast<const float4*>(
            W + (size_t)(k0 + kk) * HDIM)[cc];
        t[kk][cc*4+0] = v.x;
        t[kk][cc*4+1] = v.y;
        t[kk][cc*4+2] = v.z;
        t[kk][cc*4+3] = v.w;
    }
    __syncthreads();

    const int tx = tid & 31;
    const int ty = tid >> 5;
    #pragma unroll
    for (int r = 0; r < 128; r += 8) {
        int nl = ty + r;
        size_t o = (size_t)(blockIdx.z * HDIM + nl) * CDIM + (k0 + tx);
        g_wt[o] = __float2half_rn(t[tx][nl]);
    }
}

// ---------------------------------------------------------------------------
// Fused QKV GEMM, fp16 HMMA, N-split x2 for occupancy (R7/R9/R11-proven).
// Block: 64 rows x 192 cols, BK=32.  256 thr = 8 warps (2 m x 4 n),
// warp tile 32x48.  Grid (128, 2) = 256 CTAs -> 2 CTAs/SM resident.
// A: LDG fp32 -> cvt -> STS fp16 (reg pipelined).  B: cp.async 2-stage.
// ---------------------------------------------------------------------------
#define GQ_ROWH    40
#define GQ_A_BYTES (64*GQ_ROWH*2)              // 5120
#define GQ_B_BYTES (192*GQ_ROWH*2)             // 15360
#define GQ_STAGE   (GQ_A_BYTES + GQ_B_BYTES)   // 20480
#define GQ_SMEM    (2*GQ_STAGE)                // 40960

__device__ __forceinline__ void gemm_issueB(uint32_t smb, int stage, int ki,
                                            int n0, int tid)
{
    const int k0 = ki * 32;
    const uint32_t sb = smb + stage * GQ_STAGE + GQ_A_BYTES;
    #pragma unroll
    for (int rep = 0; rep < 3; rep++) {
        int i = tid + rep * 256;               // 0..767
        int row = i >> 2, c = i & 3;           // row 0..191
        uint32_t dst = sb + (row * GQ_ROWH + c * 8) * 2;
        CP_ASYNC16(dst, g_wt + (size_t)(n0 + row) * CDIM + k0 + c * 8);
    }
    CP_COMMIT();
}

__global__ __launch_bounds__(256, 2) void qkv_gemm_kernel(
    const float* __restrict__ x,
    const float* __restrict__ bq, const float* __restrict__ bk, const float* __restrict__ bv)
{
    extern __shared__ char dsm[];
    const uint32_t smb = smem_u32(dsm);

    const int tid  = threadIdx.x;
    const int lane = tid & 31;
    const int wid  = tid >> 5;
    const int wm   = wid & 1;
    const int wn   = wid >> 1;
    const int m0   = blockIdx.x * 64;
    const int n0   = blockIdx.y * 192;

    const int rbase = (lane & 7) + ((lane >> 3) & 1) * 8;
    const int khalf = ((lane >> 4) & 1) * 8;
    const int g = lane >> 2, t = lane & 3;

    const int arow = tid >> 2;
    const int acol = (tid & 3) * 8;
    const float* aptr = x + (size_t)(m0 + arow) * CDIM + acol;
    const uint32_t asts = (uint32_t)(arow * GQ_ROWH + acol) * 2;

    float C[2][6][4];
    #pragma unroll
    for (int a = 0; a < 2; a++)
        #pragma unroll
        for (int b = 0; b < 6; b++)
            #pragma unroll
            for (int e = 0; e < 4; e++) C[a][b][e] = 0.f;

    float4 ra0 = *reinterpret_cast<const float4*>(aptr);
    float4 ra1 = *reinterpret_cast<const float4*>(aptr + 4);
    gemm_issueB(smb, 0, 0, n0, tid);

    const int NIT = CDIM / 32;
    for (int ki = 0; ki < NIT; ki++) {
        const int st = ki & 1;
        {
            uint4 u;
            u.x = pack_h2(ra0.x, ra0.y);
            u.y = pack_h2(ra0.z, ra0.w);
            u.z = pack_h2(ra1.x, ra1.y);
            u.w = pack_h2(ra1.z, ra1.w);
            *reinterpret_cast<uint4*>(dsm + st * GQ_STAGE + asts) = u;
        }
        if (ki + 1 < NIT) {
            const float* ap = aptr + (ki + 1) * 32;
            ra0 = *reinterpret_cast<const float4*>(ap);
            ra1 = *reinterpret_cast<const float4*>(ap + 4);
            gemm_issueB(smb, st ^ 1, ki + 1, n0, tid);
            CP_WAIT1();
        } else {
            CP_WAIT0();
        }
        __syncthreads();

        const uint32_t sA = smb + st * GQ_STAGE;
        const uint32_t sB = sA + GQ_A_BYTES;

        #pragma unroll
        for (int ks = 0; ks < 2; ks++) {
            const int k0h = ks * 16 + khalf;
            uint32_t a[2][4];
            #pragma unroll
            for (int mt = 0; mt < 2; mt++) {
                int row = wm * 32 + mt * 16 + rbase;
                LDSM_X4(a[mt][0], a[mt][1], a[mt][2], a[mt][3],
                        sA + (row * GQ_ROWH + k0h) * 2);
            }
            #pragma unroll
            for (int np = 0; np < 3; np++) {
                int nrow = wn * 48 + np * 16 + rbase;
                uint32_t b0, b1, b2, b3;
                LDSM_X4(b0, b1, b2, b3, sB + (nrow * GQ_ROWH + k0h) * 2);
                #pragma unroll
                for (int mt = 0; mt < 2; mt++) {
                    mma_f16(C[mt][2*np],   a[mt][0],a[mt][1],a[mt][2],a[mt][3], b0, b2);
                    mma_f16(C[mt][2*np+1], a[mt][0],a[mt][1],a[mt][2],a[mt][3], b1, b3);
                }
            }
        }
        __syncthreads();
    }

    const float scale = 0.031880108165697356f;  // log2(e)/sqrt(2048)
    #pragma unroll
    for (int mt = 0; mt < 2; mt++) {
        #pragma unroll
        for (int nt = 0; nt < 6; nt++) {
            int colg = n0 + wn * 48 + nt * 8 + 2 * t;
            int mat  = colg >> 7;
            int c0   = colg & 127;
            const float* bias = (mat == 0) ? bq : ((mat == 1) ? bk : bv);
            __half* dst       = (mat == 0) ? g_qh : ((mat == 1) ? g_kh : g_vh);
            float sc = (mat == 0) ? scale : 1.f;
            float2 b2 = *reinterpret_cast<const float2*>(bias + c0);
            #pragma unroll
            for (int half = 0; half < 2; half++) {
                int row = m0 + wm * 32 + mt * 16 + g + 8 * half;
                float v0 = (C[mt][nt][2*half]   + b2.x) * sc;
                float v1 = (C[mt][nt][2*half+1] + b2.y) * sc;
                __half2 h; h.x = __float2half_rn(v0); h.y = __float2half_rn(v1);
                *reinterpret_cast<__half2*>(dst + (size_t)row * HDIM + c0) = h;
            }
        }
    }
}

// ---------------------------------------------------------------------------
// Flash attention, split-K x4, f32-acc S MMA, ex2 softmax, fp16 partial O,
// diagonal-tile MMA skipping, prologue-overlapped K/V loads (R11-proven).
// 128 thr = 4 warps, 64 q/CTA, key tiles of 64.  Natural CTA order.
// ---------------------------------------------------------------------------
#define A_TILE  16384                       // one 64x128 fp16 tile
#define A_BUF   (2*A_TILE)                  // K | V per stage
#define A_SMEM  (3*A_BUF)                   // 98304

__device__ __forceinline__ void attn_issue_tile(uint32_t smb, int stage,
                                                int rowbase, int kt, int tid)
{
    const uint32_t sb = smb + stage * A_BUF;
    #pragma unroll
    for (int rep = 0; rep < 16; rep++) {
        int i   = tid + rep * 128;          // 0..2047
        int arr = i >> 10;
        int rem = i & 1023;
        int r = rem >> 4, c = rem & 15;
        uint32_t dst = sb + arr * A_TILE + r * 256 + ((c ^ (r & 7)) * 16);
        const __half* src = (arr == 0 ? g_kh : g_vh)
                          + (size_t)(rowbase + kt * 64 + r) * HDIM + c * 8;
        CP_ASYNC16(dst, src);
    }
    CP_COMMIT();
}

__global__ __launch_bounds__(128) void attn_kernel()
{
    extern __shared__ char dsm[];
    const uint32_t smb = smem_u32(dsm);

    const int tid  = threadIdx.x;
    const int lane = tid & 31;
    const int w    = tid >> 5;
    const int bx   = blockIdx.x;            // q block (64 queries)
    const int h    = blockIdx.y;            // key-split index (0..3)
    const int b    = blockIdx.z;            // batch
    const int q0   = bx * 64;
    const int rowbase = b * SEQ;

    const int T  = bx + 1;                  // total key tiles for this q block
    const int kb = (h * T) >> 2;
    const int ke = ((h + 1) * T) >> 2;

    const int g = lane >> 2, t = lane & 3;
    const int rbase = (lane & 7) + ((lane >> 3) & 1) * 8;
    const int chalf = (lane >> 4) & 1;

    float o[16][4];
    #pragma unroll
    for (int n = 0; n < 16; n++)
        #pragma unroll
        for (int e = 0; e < 4; e++) o[n][e] = 0.f;
    float m0 = -INFINITY, m1 = -INFINITY, l0 = 0.f, l1 = 0.f;

    if (kb < ke) {
        attn_issue_tile(smb, 0, rowbase, kb, tid);
        if (kb + 1 < ke) attn_issue_tile(smb, 1, rowbase, kb + 1, tid);

        // Stage Q into stage-2 K region (first overwritten at kt=kb+2).
        #pragma unroll
        for (int rep = 0; rep < 8; rep++) {
            int i = tid + rep * 128;
            int r = i >> 4, c = i & 15;
            uint4 v = *reinterpret_cast<const uint4*>(
                g_qh + (size_t)(rowbase + q0 + r) * HDIM + c * 8);
            *reinterpret_cast<uint4*>(dsm + 2 * A_BUF + r * 256 + ((c ^ (r & 7)) * 16)) = v;
        }
        __syncthreads();

        uint32_t qf[8][4];
        {
            const uint32_t qb = smb + 2 * A_BUF;
            int row = w * 16 + rbase;
            #pragma unroll
            for (int kc = 0; kc < 8; kc++) {
                int ch = 2 * kc + chalf;
                LDSM_X4(qf[kc][0], qf[kc][1], qf[kc][2], qf[kc][3],
                        qb + row * 256 + ((ch ^ (row & 7)) * 16));
            }
        }

        for (int kt = kb; kt < ke; kt++) {
            const int st = (kt - kb) % 3;
            if (kt + 1 < ke) CP_WAIT1(); else CP_WAIT0();
            __syncthreads();
            if (kt + 2 < ke) attn_issue_tile(smb, (st + 2) % 3, rowbase, kt + 2, tid);

            const uint32_t kbuf = smb + st * A_BUF;
            const uint32_t vbuf = kbuf + A_TILE;
            const bool diag = (kt == bx);

            float s[8][4];
            #pragma unroll
            for (int j = 0; j < 8; j++)
                #pragma unroll
                for (int e = 0; e < 4; e++) s[j][e] = 0.f;

            #pragma unroll
            for (int jp = 0; jp < 4; jp++) {
                if (diag && jp > w) break;
                int krow = jp * 16 + rbase;
                #pragma unroll
                for (int kc = 0; kc < 8; kc++) {
                    int ch = 2 * kc + chalf;
                    uint32_t b0, b1, b2, b3;
                    LDSM_X4(b0, b1, b2, b3, kbuf + krow * 256 + ((ch ^ (krow & 7)) * 16));
                    mma_f16(s[2*jp],   qf[kc][0], qf[kc][1], qf[kc][2], qf[kc][3], b0, b2);
                    mma_f16(s[2*jp+1], qf[kc][0], qf[kc][1], qf[kc][2], qf[kc][3], b1, b3);
                }
            }

            if (diag) {
                #pragma unroll
                for (int j = 0; j < 8; j++) {
                    int key = 8 * j + 2 * t;
                    int qr0 = 16 * w + g, qr1 = qr0 + 8;
                    if (key     > qr0) s[j][0] = -INFINITY;
                    if (key + 1 > qr0) s[j][1] = -INFINITY;
                    if (key     > qr1) s[j][2] = -INFINITY;
                    if (key + 1 > qr1) s[j][3] = -INFINITY;
                }
            }

            float r0 = -INFINITY, r1 = -INFINITY;
            #pragma unroll
            for (int j = 0; j < 8; j++) {
                r0 = fmaxf(r0, fmaxf(s[j][0], s[j][1]));
                r1 = fmaxf(r1, fmaxf(s[j][2], s[j][3]));
            }
            r0 = fmaxf(r0, __shfl_xor_sync(0xffffffffu, r0, 1));
            r0 = fmaxf(r0, __shfl_xor_sync(0xffffffffu, r0, 2));
            r1 = fmaxf(r1, __shfl_xor_sync(0xffffffffu, r1, 1));
            r1 = fmaxf(r1, __shfl_xor_sync(0xffffffffu, r1, 2));

            float mn0 = fmaxf(m0, r0), mn1 = fmaxf(m1, r1);
            float cr0 = ex2f(m0 - mn0), cr1 = ex2f(m1 - mn1);

            float rs0 = 0.f, rs1 = 0.f;
            #pragma unroll
            for (int j = 0; j < 8; j++) {
                s[j][0] = ex2f(s[j][0] - mn0);
                s[j][1] = ex2f(s[j][1] - mn0);
                s[j][2] = ex2f(s[j][2] - mn1);
                s[j][3] = ex2f(s[j][3] - mn1);
                rs0 += s[j][0] + s[j][1];
                rs1 += s[j][2] + s[j][3];
            }
            rs0 += __shfl_xor_sync(0xffffffffu, rs0, 1);
            rs0 += __shfl_xor_sync(0xffffffffu, rs0, 2);
            rs1 += __shfl_xor_sync(0xffffffffu, rs1, 1);
            rs1 += __shfl_xor_sync(0xffffffffu, rs1, 2);

            l0 = l0 * cr0 + rs0;
            l1 = l1 * cr1 + rs1;
            m0 = mn0; m1 = mn1;
            #pragma unroll
            for (int n = 0; n < 16; n++) {
                o[n][0] *= cr0; o[n][1] *= cr0;
                o[n][2] *= cr1; o[n][3] *= cr1;
            }

            uint32_t ap[4][4];
            #pragma unroll
            for (int u = 0; u < 4; u++)
                #pragma unroll
                for (int half = 0; half < 2; half++)
                    #pragma unroll
                    for (int sub = 0; sub < 2; sub++)
                        ap[u][half + 2*sub] = pack_h2(s[2*u + sub][2*half],
                                                      s[2*u + sub][2*half + 1]);

            #pragma unroll
            for (int u = 0; u < 4; u++) {
                if (diag && u > w) break;
                int krow = u * 16 + rbase;
                #pragma unroll
                for (int ntp = 0; ntp < 8; ntp++) {
                    int ch = 2 * ntp + chalf;
                    uint32_t h0, h1, h2, h3;
                    LDSM_X4T(h0, h1, h2, h3, vbuf + krow * 256 + ((ch ^ (krow & 7)) * 16));
                    mma_f16(o[2*ntp],   ap[u][0],ap[u][1],ap[u][2],ap[u][3], h0, h1);
                    mma_f16(o[2*ntp+1], ap[u][0],ap[u][1],ap[u][2],ap[u][3], h2, h3);
                }
            }
        }
    }

    int row0 = rowbase + q0 + 16 * w + g;
    __half* po = g_poh[h];
    #pragma unroll
    for (int j = 0; j < 16; j++) {
        int col = 8 * j + 2 * t;
        *reinterpret_cast<uint32_t*>(po + (size_t)row0 * HDIM + col)       = pack_h2(o[j][0], o[j][1]);
        *reinterpret_cast<uint32_t*>(po + (size_t)(row0 + 8) * HDIM + col) = pack_h2(o[j][2], o[j][3]);
    }
    if (t == 0) {
        float2 a; a.x = m0; a.y = l0;
        float2 c; c.x = m1; c.y = l1;
        g_pml[h][row0]     = a;
        g_pml[h][row0 + 8] = c;
    }
}

// ---------------------------------------------------------------------------
// Combine the four key-split fp16 partials -> final fp32 output.
// Finer grain: one uint2 (4 halves) per split per thread, grid 2048x128,
// doubling resident parallelism on this latency-bound kernel.
// ---------------------------------------------------------------------------
__global__ __launch_bounds__(128) void combine_kernel(float* __restrict__ out)
{
    int gid = blockIdx.x * 128 + threadIdx.x;   // < ROWS*32 (uint2 = 4 halves)
    int q = gid >> 5;
    float2 ml[NSPLIT];
    float M = -INFINITY;
    #pragma unroll
    for (int i = 0; i < NSPLIT; i++) { ml[i] = g_pml[i][q]; M = fmaxf(M, ml[i].x); }
    float e[NSPLIT], den = 0.f;
    #pragma unroll
    for (int i = 0; i < NSPLIT; i++) { e[i] = ex2f(ml[i].x - M); den += ml[i].y * e[i]; }
    float inv = 1.f / den;

    float acc[4];
    #pragma unroll
    for (int j = 0; j < 4; j++) acc[j] = 0.f;
    #pragma unroll
    for (int i = 0; i < NSPLIT; i++) {
        uint2 u = reinterpret_cast<const uint2*>(g_poh[i])[gid];
        float2 f0 = __half22float2(*reinterpret_cast<const __half2*>(&u.x));
        float2 f1 = __half22float2(*reinterpret_cast<const __half2*>(&u.y));
        acc[0] = fmaf(f0.x, e[i], acc[0]);
        acc[1] = fmaf(f0.y, e[i], acc[1]);
        acc[2] = fmaf(f1.x, e[i], acc[2]);
        acc[3] = fmaf(f1.y, e[i], acc[3]);
    }
    float4 r;
    r.x = acc[0] * inv; r.y = acc[1] * inv; r.z = acc[2] * inv; r.w = acc[3] * inv;
    reinterpret_cast<float4*>(out)[gid] = r;
}

// ---------------------------------------------------------------------------
extern "C" void kernel_launch(void* const* d_in, const int* in_sizes, int n_in,
                              void* d_out, int out_size)
{
    const float* x  = (const float*)d_in[0];
    const float* wq = (const float*)d_in[1];
    const float* bq = (const float*)d_in[2];
    const float* wk = (const float*)d_in[3];
    const float* bk = (const float*)d_in[4];
    const float* wv = (const float*)d_in[5];
    const float* bv = (const float*)d_in[6];
    float* out = (float*)d_out;

    cudaFuncSetAttribute(qkv_gemm_kernel,
                         cudaFuncAttributeMaxDynamicSharedMemorySize, GQ_SMEM);
    cudaFuncSetAttribute(attn_kernel,
                         cudaFuncAttributeMaxDynamicSharedMemorySize, A_SMEM);

    prep_w_kernel<<<dim3(CDIM/32, 1, 3), 256>>>(wq, wk, wv);
    qkv_gemm_kernel<<<dim3(ROWS/64, 2), 256, GQ_SMEM>>>(x, bq, bk, bv);
    attn_kernel<<<dim3(SEQ/64, NSPLIT, BATCH), 128, A_SMEM>>>();
    combine_kernel<<<ROWS*32/128, 128>>>(out);
}

// round 17
// speedup vs baseline: 1.1102x; 1.0452x over previous
#include <cuda_runtime.h>
#include <cuda_fp16.h>
#include <cstdint>
#include <math.h>

#define BATCH 4
#define SEQ   2048
#define CDIM  2048
#define HDIM  128
#define ROWS  (BATCH*SEQ)
#define NSPLIT 4

// ---------------------------------------------------------------------------
// Device scratch (allocation-free)
// ---------------------------------------------------------------------------
__device__ __align__(16) __half g_wt[(size_t)3*HDIM*CDIM];   // W^T fp16 [384][2048]
__device__ __align__(16) __half g_qh[(size_t)ROWS*HDIM];     // q*scale*log2e fp16
__device__ __align__(16) __half g_kh[(size_t)ROWS*HDIM];     // k fp16
__device__ __align__(16) __half g_vh[(size_t)ROWS*HDIM];     // v fp16
__device__ __align__(16) __half g_poh[NSPLIT][(size_t)ROWS*HDIM]; // partial O fp16
__device__ float2 g_pml[NSPLIT][ROWS];                       // partial (m, l), m in log2 domain

// ---------------------------------------------------------------------------
// Helpers (vanilla sm_80-era PTX: ldmatrix / mma.sync / cp.async)
// ---------------------------------------------------------------------------
__device__ __forceinline__ uint32_t smem_u32(const void* p) {
    uint32_t a;
    asm("{ .reg .u64 t; cvta.to.shared.u64 t, %1; cvt.u32.u64 %0, t; }"
        : "=r"(a) : "l"(p));
    return a;
}
#define CP_ASYNC16(dst, src) \
    asm volatile("cp.async.cg.shared.global [%0], [%1], 16;" \
                 :: "r"(dst), "l"(src) : "memory")
#define CP_COMMIT() asm volatile("cp.async.commit_group;" ::: "memory")
#define CP_WAIT1()  asm volatile("cp.async.wait_group 1;" ::: "memory")
#define CP_WAIT0()  asm volatile("cp.async.wait_group 0;" ::: "memory")

#define LDSM_X4(r0,r1,r2,r3,addr) \
    asm volatile("ldmatrix.sync.aligned.m8n8.x4.shared.b16 {%0,%1,%2,%3}, [%4];" \
                 : "=r"(r0),"=r"(r1),"=r"(r2),"=r"(r3) : "r"(addr))
#define LDSM_X4T(r0,r1,r2,r3,addr) \
    asm volatile("ldmatrix.sync.aligned.m8n8.x4.trans.shared.b16 {%0,%1,%2,%3}, [%4];" \
                 : "=r"(r0),"=r"(r1),"=r"(r2),"=r"(r3) : "r"(addr))

__device__ __forceinline__ void mma_f16(float c[4], uint32_t a0, uint32_t a1,
                                        uint32_t a2, uint32_t a3,
                                        uint32_t b0, uint32_t b1)
{
    asm volatile(
        "mma.sync.aligned.m16n8k16.row.col.f32.f16.f16.f32 "
        "{%0,%1,%2,%3},{%4,%5,%6,%7},{%8,%9},{%0,%1,%2,%3};"
        : "+f"(c[0]), "+f"(c[1]), "+f"(c[2]), "+f"(c[3])
        : "r"(a0), "r"(a1), "r"(a2), "r"(a3), "r"(b0), "r"(b1));
}
// pack {lo, hi} floats -> f16x2 register
__device__ __forceinline__ uint32_t pack_h2(float lo, float hi) {
    uint32_t d;
    asm("cvt.rn.f16x2.f32 %0, %1, %2;" : "=r"(d) : "f"(hi), "f"(lo));
    return d;
}
__device__ __forceinline__ float ex2f(float x) {
    float r;
    asm("ex2.approx.f32 %0, %1;" : "=f"(r) : "f"(x));
    return r;
}

// ---------------------------------------------------------------------------
// Prep: transpose W[2048][128] -> W^T fp16 rows [z*128 + n][k]
// ---------------------------------------------------------------------------
__global__ __launch_bounds__(256) void prep_w_kernel(
    const float* __restrict__ wq, const float* __restrict__ wk, const float* __restrict__ wv)
{
    __shared__ float t[32][129];
    const float* W = (blockIdx.z == 0) ? wq : ((blockIdx.z == 1) ? wk : wv);
    const int k0 = blockIdx.x * 32;
    const int tid = threadIdx.x;

    #pragma unroll
    for (int rep = 0; rep < 4; rep++) {
        int i  = tid + rep * 256;          // 0..1023
        int kk = i >> 5, cc = i & 31;
        float4 v = reinterpret_cast<const float4*>(
            W + (size_t)(k0 + kk) * HDIM)[cc];
        t[kk][cc*4+0] = v.x;
        t[kk][cc*4+1] = v.y;
        t[kk][cc*4+2] = v.z;
        t[kk][cc*4+3] = v.w;
    }
    __syncthreads();

    const int tx = tid & 31;
    const int ty = tid >> 5;
    #pragma unroll
    for (int r = 0; r < 128; r += 8) {
        int nl = ty + r;
        size_t o = (size_t)(blockIdx.z * HDIM + nl) * CDIM + (k0 + tx);
        g_wt[o] = __float2half_rn(t[tx][nl]);
    }
}

// ---------------------------------------------------------------------------
// Fused QKV GEMM, fp16 HMMA, N-split x2, BK=32, 3-stage cp.async ring with
// ONE __syncthreads per K-iter (issue-after-barrier).  2 CTAs/SM resident.
// Block: 64 rows x 192 cols.  256 thr = 8 warps (2 m x 4 n), warp tile 32x48.
// ---------------------------------------------------------------------------
#define GQ_ROWH    40
#define GQ_A_BYTES (64*GQ_ROWH*2)              // 5120
#define GQ_B_BYTES (192*GQ_ROWH*2)             // 15360
#define GQ_STAGE   (GQ_A_BYTES + GQ_B_BYTES)   // 20480
#define GQ_SMEM    (3*GQ_STAGE)                // 61440

__device__ __forceinline__ void gemm_issueB(uint32_t smb, int stage, int ki,
                                            int n0, int tid)
{
    const int k0 = ki * 32;
    const uint32_t sb = smb + stage * GQ_STAGE + GQ_A_BYTES;
    #pragma unroll
    for (int rep = 0; rep < 3; rep++) {
        int i = tid + rep * 256;               // 0..767
        int row = i >> 2, c = i & 3;           // row 0..191
        uint32_t dst = sb + (row * GQ_ROWH + c * 8) * 2;
        CP_ASYNC16(dst, g_wt + (size_t)(n0 + row) * CDIM + k0 + c * 8);
    }
    CP_COMMIT();
}

__global__ __launch_bounds__(256, 2) void qkv_gemm_kernel(
    const float* __restrict__ x,
    const float* __restrict__ bq, const float* __restrict__ bk, const float* __restrict__ bv)
{
    extern __shared__ char dsm[];
    const uint32_t smb = smem_u32(dsm);

    const int tid  = threadIdx.x;
    const int lane = tid & 31;
    const int wid  = tid >> 5;
    const int wm   = wid & 1;
    const int wn   = wid >> 1;
    const int m0   = blockIdx.x * 64;
    const int n0   = blockIdx.y * 192;

    const int rbase = (lane & 7) + ((lane >> 3) & 1) * 8;
    const int khalf = ((lane >> 4) & 1) * 8;
    const int g = lane >> 2, t = lane & 3;

    const int arow = tid >> 2;
    const int acol = (tid & 3) * 8;
    const float* aptr = x + (size_t)(m0 + arow) * CDIM + acol;
    const uint32_t asts = (uint32_t)(arow * GQ_ROWH + acol) * 2;

    float C[2][6][4];
    #pragma unroll
    for (int a = 0; a < 2; a++)
        #pragma unroll
        for (int b = 0; b < 6; b++)
            #pragma unroll
            for (int e = 0; e < 4; e++) C[a][b][e] = 0.f;

    float4 ra0 = *reinterpret_cast<const float4*>(aptr);
    float4 ra1 = *reinterpret_cast<const float4*>(aptr + 4);
    gemm_issueB(smb, 0, 0, n0, tid);
    gemm_issueB(smb, 1, 1, n0, tid);

    const int NIT = CDIM / 32;                  // 64
    for (int ki = 0; ki < NIT; ki++) {
        const int st = ki % 3;
        // Store A regs into stage st.  Safe: stage st was last read at
        // compute(ki-3), which precedes sync(ki-1) in program order.
        {
            uint4 u;
            u.x = pack_h2(ra0.x, ra0.y);
            u.y = pack_h2(ra0.z, ra0.w);
            u.z = pack_h2(ra1.x, ra1.y);
            u.w = pack_h2(ra1.z, ra1.w);
            *reinterpret_cast<uint4*>(dsm + st * GQ_STAGE + asts) = u;
        }
        if (ki + 1 < NIT) {
            const float* ap = aptr + (ki + 1) * 32;
            ra0 = *reinterpret_cast<const float4*>(ap);
            ra1 = *reinterpret_cast<const float4*>(ap + 4);
            CP_WAIT1();                         // group ki done; ki+1 pending
        } else {
            CP_WAIT0();
        }
        __syncthreads();
        // Issue B for ki+2 into stage (ki+2)%3 = (ki-1)%3: its last reader
        // was compute(ki-1), which precedes sync(ki) in program order.
        if (ki + 2 < NIT) gemm_issueB(smb, (ki + 2) % 3, ki + 2, n0, tid);

        const uint32_t sA = smb + st * GQ_STAGE;
        const uint32_t sB = sA + GQ_A_BYTES;

        #pragma unroll
        for (int ks = 0; ks < 2; ks++) {
            const int k0h = ks * 16 + khalf;
            uint32_t a[2][4];
            #pragma unroll
            for (int mt = 0; mt < 2; mt++) {
                int row = wm * 32 + mt * 16 + rbase;
                LDSM_X4(a[mt][0], a[mt][1], a[mt][2], a[mt][3],
                        sA + (row * GQ_ROWH + k0h) * 2);
            }
            #pragma unroll
            for (int np = 0; np < 3; np++) {
                int nrow = wn * 48 + np * 16 + rbase;
                uint32_t b0, b1, b2, b3;
                LDSM_X4(b0, b1, b2, b3, sB + (nrow * GQ_ROWH + k0h) * 2);
                #pragma unroll
                for (int mt = 0; mt < 2; mt++) {
                    mma_f16(C[mt][2*np],   a[mt][0],a[mt][1],a[mt][2],a[mt][3], b0, b2);
                    mma_f16(C[mt][2*np+1], a[mt][0],a[mt][1],a[mt][2],a[mt][3], b1, b3);
                }
            }
        }
    }

    const float scale = 0.031880108165697356f;  // log2(e)/sqrt(2048)
    #pragma unroll
    for (int mt = 0; mt < 2; mt++) {
        #pragma unroll
        for (int nt = 0; nt < 6; nt++) {
            int colg = n0 + wn * 48 + nt * 8 + 2 * t;
            int mat  = colg >> 7;
            int c0   = colg & 127;
            const float* bias = (mat == 0) ? bq : ((mat == 1) ? bk : bv);
            __half* dst       = (mat == 0) ? g_qh : ((mat == 1) ? g_kh : g_vh);
            float sc = (mat == 0) ? scale : 1.f;
            float2 b2 = *reinterpret_cast<const float2*>(bias + c0);
            #pragma unroll
            for (int half = 0; half < 2; half++) {
                int row = m0 + wm * 32 + mt * 16 + g + 8 * half;
                float v0 = (C[mt][nt][2*half]   + b2.x) * sc;
                float v1 = (C[mt][nt][2*half+1] + b2.y) * sc;
                __half2 h; h.x = __float2half_rn(v0); h.y = __float2half_rn(v1);
                *reinterpret_cast<__half2*>(dst + (size_t)row * HDIM + c0) = h;
            }
        }
    }
}

// ---------------------------------------------------------------------------
// Flash attention, split-K x4, f32-acc S MMA, ex2 softmax, fp16 partial O,
// diagonal-tile MMA skipping, prologue-overlapped K/V loads (R11/R16-proven).
// 128 thr = 4 warps, 64 q/CTA, key tiles of 64.  Natural CTA order.
// ---------------------------------------------------------------------------
#define A_TILE  16384                       // one 64x128 fp16 tile
#define A_BUF   (2*A_TILE)                  // K | V per stage
#define A_SMEM  (3*A_BUF)                   // 98304

__device__ __forceinline__ void attn_issue_tile(uint32_t smb, int stage,
                                                int rowbase, int kt, int tid)
{
    const uint32_t sb = smb + stage * A_BUF;
    #pragma unroll
    for (int rep = 0; rep < 16; rep++) {
        int i   = tid + rep * 128;          // 0..2047
        int arr = i >> 10;
        int rem = i & 1023;
        int r = rem >> 4, c = rem & 15;
        uint32_t dst = sb + arr * A_TILE + r * 256 + ((c ^ (r & 7)) * 16);
        const __half* src = (arr == 0 ? g_kh : g_vh)
                          + (size_t)(rowbase + kt * 64 + r) * HDIM + c * 8;
        CP_ASYNC16(dst, src);
    }
    CP_COMMIT();
}

__global__ __launch_bounds__(128) void attn_kernel()
{
    extern __shared__ char dsm[];
    const uint32_t smb = smem_u32(dsm);

    const int tid  = threadIdx.x;
    const int lane = tid & 31;
    const int w    = tid >> 5;
    const int bx   = blockIdx.x;            // q block (64 queries)
    const int h    = blockIdx.y;            // key-split index (0..3)
    const int b    = blockIdx.z;            // batch
    const int q0   = bx * 64;
    const int rowbase = b * SEQ;

    const int T  = bx + 1;                  // total key tiles for this q block
    const int kb = (h * T) >> 2;
    const int ke = ((h + 1) * T) >> 2;

    const int g = lane >> 2, t = lane & 3;
    const int rbase = (lane & 7) + ((lane >> 3) & 1) * 8;
    const int chalf = (lane >> 4) & 1;

    float o[16][4];
    #pragma unroll
    for (int n = 0; n < 16; n++)
        #pragma unroll
        for (int e = 0; e < 4; e++) o[n][e] = 0.f;
    float m0 = -INFINITY, m1 = -INFINITY, l0 = 0.f, l1 = 0.f;

    if (kb < ke) {
        attn_issue_tile(smb, 0, rowbase, kb, tid);
        if (kb + 1 < ke) attn_issue_tile(smb, 1, rowbase, kb + 1, tid);

        // Stage Q into stage-2 K region (first overwritten at kt=kb+2).
        #pragma unroll
        for (int rep = 0; rep < 8; rep++) {
            int i = tid + rep * 128;
            int r = i >> 4, c = i & 15;
            uint4 v = *reinterpret_cast<const uint4*>(
                g_qh + (size_t)(rowbase + q0 + r) * HDIM + c * 8);
            *reinterpret_cast<uint4*>(dsm + 2 * A_BUF + r * 256 + ((c ^ (r & 7)) * 16)) = v;
        }
        __syncthreads();

        uint32_t qf[8][4];
        {
            const uint32_t qb = smb + 2 * A_BUF;
            int row = w * 16 + rbase;
            #pragma unroll
            for (int kc = 0; kc < 8; kc++) {
                int ch = 2 * kc + chalf;
                LDSM_X4(qf[kc][0], qf[kc][1], qf[kc][2], qf[kc][3],
                        qb + row * 256 + ((ch ^ (row & 7)) * 16));
            }
        }

        for (int kt = kb; kt < ke; kt++) {
            const int st = (kt - kb) % 3;
            if (kt + 1 < ke) CP_WAIT1(); else CP_WAIT0();
            __syncthreads();
            if (kt + 2 < ke) attn_issue_tile(smb, (st + 2) % 3, rowbase, kt + 2, tid);

            const uint32_t kbuf = smb + st * A_BUF;
            const uint32_t vbuf = kbuf + A_TILE;
            const bool diag = (kt == bx);

            float s[8][4];
            #pragma unroll
            for (int j = 0; j < 8; j++)
                #pragma unroll
                for (int e = 0; e < 4; e++) s[j][e] = 0.f;

            #pragma unroll
            for (int jp = 0; jp < 4; jp++) {
                if (diag && jp > w) break;
                int krow = jp * 16 + rbase;
                #pragma unroll
                for (int kc = 0; kc < 8; kc++) {
                    int ch = 2 * kc + chalf;
                    uint32_t b0, b1, b2, b3;
                    LDSM_X4(b0, b1, b2, b3, kbuf + krow * 256 + ((ch ^ (krow & 7)) * 16));
                    mma_f16(s[2*jp],   qf[kc][0], qf[kc][1], qf[kc][2], qf[kc][3], b0, b2);
                    mma_f16(s[2*jp+1], qf[kc][0], qf[kc][1], qf[kc][2], qf[kc][3], b1, b3);
                }
            }

            if (diag) {
                #pragma unroll
                for (int j = 0; j < 8; j++) {
                    int key = 8 * j + 2 * t;
                    int qr0 = 16 * w + g, qr1 = qr0 + 8;
                    if (key     > qr0) s[j][0] = -INFINITY;
                    if (key + 1 > qr0) s[j][1] = -INFINITY;
                    if (key     > qr1) s[j][2] = -INFINITY;
                    if (key + 1 > qr1) s[j][3] = -INFINITY;
                }
            }

            float r0 = -INFINITY, r1 = -INFINITY;
            #pragma unroll
            for (int j = 0; j < 8; j++) {
                r0 = fmaxf(r0, fmaxf(s[j][0], s[j][1]));
                r1 = fmaxf(r1, fmaxf(s[j][2], s[j][3]));
            }
            r0 = fmaxf(r0, __shfl_xor_sync(0xffffffffu, r0, 1));
            r0 = fmaxf(r0, __shfl_xor_sync(0xffffffffu, r0, 2));
            r1 = fmaxf(r1, __shfl_xor_sync(0xffffffffu, r1, 1));
            r1 = fmaxf(r1, __shfl_xor_sync(0xffffffffu, r1, 2));

            float mn0 = fmaxf(m0, r0), mn1 = fmaxf(m1, r1);
            float cr0 = ex2f(m0 - mn0), cr1 = ex2f(m1 - mn1);

            float rs0 = 0.f, rs1 = 0.f;
            #pragma unroll
            for (int j = 0; j < 8; j++) {
                s[j][0] = ex2f(s[j][0] - mn0);
                s[j][1] = ex2f(s[j][1] - mn0);
                s[j][2] = ex2f(s[j][2] - mn1);
                s[j][3] = ex2f(s[j][3] - mn1);
                rs0 += s[j][0] + s[j][1];
                rs1 += s[j][2] + s[j][3];
            }
            rs0 += __shfl_xor_sync(0xffffffffu, rs0, 1);
            rs0 += __shfl_xor_sync(0xffffffffu, rs0, 2);
            rs1 += __shfl_xor_sync(0xffffffffu, rs1, 1);
            rs1 += __shfl_xor_sync(0xffffffffu, rs1, 2);

            l0 = l0 * cr0 + rs0;
            l1 = l1 * cr1 + rs1;
            m0 = mn0; m1 = mn1;
            #pragma unroll
            for (int n = 0; n < 16; n++) {
                o[n][0] *= cr0; o[n][1] *= cr0;
                o[n][2] *= cr1; o[n][3] *= cr1;
            }

            uint32_t ap[4][4];
            #pragma unroll
            for (int u = 0; u < 4; u++)
                #pragma unroll
                for (int half = 0; half < 2; half++)
                    #pragma unroll
                    for (int sub = 0; sub < 2; sub++)
                        ap[u][half + 2*sub] = pack_h2(s[2*u + sub][2*half],
                                                      s[2*u + sub][2*half + 1]);

            #pragma unroll
            for (int u = 0; u < 4; u++) {
                if (diag && u > w) break;
                int krow = u * 16 + rbase;
                #pragma unroll
                for (int ntp = 0; ntp < 8; ntp++) {
                    int ch = 2 * ntp + chalf;
                    uint32_t h0, h1, h2, h3;
                    LDSM_X4T(h0, h1, h2, h3, vbuf + krow * 256 + ((ch ^ (krow & 7)) * 16));
                    mma_f16(o[2*ntp],   ap[u][0],ap[u][1],ap[u][2],ap[u][3], h0, h1);
                    mma_f16(o[2*ntp+1], ap[u][0],ap[u][1],ap[u][2],ap[u][3], h2, h3);
                }
            }
        }
    }

    int row0 = rowbase + q0 + 16 * w + g;
    __half* po = g_poh[h];
    #pragma unroll
    for (int j = 0; j < 16; j++) {
        int col = 8 * j + 2 * t;
        *reinterpret_cast<uint32_t*>(po + (size_t)row0 * HDIM + col)       = pack_h2(o[j][0], o[j][1]);
        *reinterpret_cast<uint32_t*>(po + (size_t)(row0 + 8) * HDIM + col) = pack_h2(o[j][2], o[j][3]);
    }
    if (t == 0) {
        float2 a; a.x = m0; a.y = l0;
        float2 c; c.x = m1; c.y = l1;
        g_pml[h][row0]     = a;
        g_pml[h][row0 + 8] = c;
    }
}

// ---------------------------------------------------------------------------
// Combine the four key-split fp16 partials -> final fp32 output (R16 form).
// ---------------------------------------------------------------------------
__global__ __launch_bounds__(128) void combine_kernel(float* __restrict__ out)
{
    int gid = blockIdx.x * 128 + threadIdx.x;   // < ROWS*32 (uint2 = 4 halves)
    int q = gid >> 5;
    float2 ml[NSPLIT];
    float M = -INFINITY;
    #pragma unroll
    for (int i = 0; i < NSPLIT; i++) { ml[i] = g_pml[i][q]; M = fmaxf(M, ml[i].x); }
    float e[NSPLIT], den = 0.f;
    #pragma unroll
    for (int i = 0; i < NSPLIT; i++) { e[i] = ex2f(ml[i].x - M); den += ml[i].y * e[i]; }
    float inv = 1.f / den;

    float acc[4];
    #pragma unroll
    for (int j = 0; j < 4; j++) acc[j] = 0.f;
    #pragma unroll
    for (int i = 0; i < NSPLIT; i++) {
        uint2 u = reinterpret_cast<const uint2*>(g_poh[i])[gid];
        float2 f0 = __half22float2(*reinterpret_cast<const __half2*>(&u.x));
        float2 f1 = __half22float2(*reinterpret_cast<const __half2*>(&u.y));
        acc[0] = fmaf(f0.x, e[i], acc[0]);
        acc[1] = fmaf(f0.y, e[i], acc[1]);
        acc[2] = fmaf(f1.x, e[i], acc[2]);
        acc[3] = fmaf(f1.y, e[i], acc[3]);
    }
    float4 r;
    r.x = acc[0] * inv; r.y = acc[1] * inv; r.z = acc[2] * inv; r.w = acc[3] * inv;
    reinterpret_cast<float4*>(out)[gid] = r;
}

// ---------------------------------------------------------------------------
extern "C" void kernel_launch(void* const* d_in, const int* in_sizes, int n_in,
                              void* d_out, int out_size)
{
    const float* x  = (const float*)d_in[0];
    const float* wq = (const float*)d_in[1];
    const float* bq = (const float*)d_in[2];
    const float* wk = (const float*)d_in[3];
    const float* bk = (const float*)d_in[4];
    const float* wv = (const float*)d_in[5];
    const float* bv = (const float*)d_in[6];
    float* out = (float*)d_out;

    cudaFuncSetAttribute(qkv_gemm_kernel,
                         cudaFuncAttributeMaxDynamicSharedMemorySize, GQ_SMEM);
    cudaFuncSetAttribute(attn_kernel,
                         cudaFuncAttributeMaxDynamicSharedMemorySize, A_SMEM);

    prep_w_kernel<<<dim3(CDIM/32, 1, 3), 256>>>(wq, wk, wv);
    qkv_gemm_kernel<<<dim3(ROWS/64, 2), 256, GQ_SMEM>>>(x, bq, bk, bv);
    attn_kernel<<<dim3(SEQ/64, NSPLIT, BATCH), 128, A_SMEM>>>();
    combine_kernel<<<ROWS*32/128, 128>>>(out);
}